// round 14
// baseline (speedup 1.0000x reference)
#include <cuda_runtime.h>
#include <cuda_bf16.h>
#include <math.h>
#include <stdint.h>

// ---------------- problem constants ----------------
#define BB    8
#define LSEQ  1024            // 2*L_IN
#define ROWS  (BB*LSEQ)       // 8192 tokens
#define CC    512
#define DI    1024
#define DS    16
#define NDEPTH 4

// weight-pack offsets (elements) in the converted bf16 weight bank
#define OFF_W1   0
#define SZ_W1    (512*1024)
#define OFF_W2   (OFF_W1 + SZ_W1)
#define SZ_W2    (512*512)
#define OFF_IP   (OFF_W2 + SZ_W2)
#define SZ_IP    (2048*512)
#define OFF_XP   (OFF_IP + 4*SZ_IP)
#define SZ_XP    (128*1024)
#define OFF_OP   (OFF_XP + 4*SZ_XP)
#define SZ_OP    (512*1024)
#define WB_TOTAL (OFF_OP + 4*SZ_OP)   // 7,602,176

// ---------------- scratch (device globals; no allocs allowed) ----------------
__device__ float g_up_tmp[4096*1024];   // up GEMM raw output
__device__ float g_h    [ROWS*CC];      // h1 (pre-rmsnorm)
__device__ float g_x    [ROWS*CC];      // residual stream
__device__ float g_xz   [ROWS*2*DI];    // in_proj out (xc_raw | z)
__device__ float g_xc   [ROWS*DI];      // conv+silu out f32 (scan u)
__device__ float g_xdbc [ROWS*128];     // x_proj out (dtp|B|C|pad), ld=128
__device__ float g_xpart[4*ROWS*128];   // x_proj split-K partials

// bf16 hi/lo operand buffers
__device__ __align__(16) __nv_bfloat16 g_mo_h[4096*512],  g_mo_l[4096*512];
__device__ __align__(16) __nv_bfloat16 g_cat_h[ROWS*1024], g_cat_l[ROWS*1024]; // [up|skip]
__device__ __align__(16) __nv_bfloat16 g_hh[ROWS*512],    g_hl[ROWS*512];
__device__ __align__(16) __nv_bfloat16 g_lnh[ROWS*512],   g_lnl[ROWS*512];
__device__ __align__(16) __nv_bfloat16 g_xch[ROWS*1024],  g_xcl[ROWS*1024];
__device__ __align__(16) __nv_bfloat16 g_yh[ROWS*1024],   g_yl[ROWS*1024];
__device__ __align__(16) __nv_bfloat16 g_wupT_h[1024*512], g_wupT_l[1024*512];
__device__ __align__(16) __nv_bfloat16 g_wb_h[WB_TOTAL],   g_wb_l[WB_TOTAL];

// ---------------- helpers ----------------
__device__ __forceinline__ float softplusf(float x) {
    return (x > 20.f) ? x : log1pf(__expf(x));
}
__device__ __forceinline__ float siluf(float x) {
    return x / (1.f + __expf(-x));
}

__device__ __forceinline__ uint32_t smem_u32(const void* p) {
    uint32_t a;
    asm("{ .reg .u64 t; cvta.to.shared.u64 t, %1; cvt.u32.u64 %0, t; }"
        : "=r"(a) : "l"(p));
    return a;
}

__device__ __forceinline__ void split1(float v, __nv_bfloat16& h, __nv_bfloat16& l) {
    h = __float2bfloat16(v);
    l = __float2bfloat16(v - __bfloat162float(h));
}

// split f32x4 into bf16 hi / lo pairs (packed bf16x2 words, .x in low half)
__device__ __forceinline__ void split4(float4 v, uint32_t& h01, uint32_t& h23,
                                       uint32_t& l01, uint32_t& l23) {
    __nv_bfloat162 h0 = __float22bfloat162_rn(make_float2(v.x, v.y));
    __nv_bfloat162 h1 = __float22bfloat162_rn(make_float2(v.z, v.w));
    float2 f0 = __bfloat1622float2(h0), f1 = __bfloat1622float2(h1);
    __nv_bfloat162 l0 = __float22bfloat162_rn(make_float2(v.x - f0.x, v.y - f0.y));
    __nv_bfloat162 l1 = __float22bfloat162_rn(make_float2(v.z - f1.x, v.w - f1.y));
    h01 = *(uint32_t*)&h0; h23 = *(uint32_t*)&h1;
    l01 = *(uint32_t*)&l0; l23 = *(uint32_t*)&l1;
}

__device__ __forceinline__ void ldsm4(uint32_t* r, uint32_t addr) {
    asm volatile("ldmatrix.sync.aligned.m8n8.x4.shared.b16 {%0,%1,%2,%3}, [%4];"
        : "=r"(r[0]), "=r"(r[1]), "=r"(r[2]), "=r"(r[3]) : "r"(addr));
}

__device__ __forceinline__ void mma_bf16(float* c, const uint32_t* a, const uint32_t* b) {
    asm volatile("mma.sync.aligned.m16n8k16.row.col.f32.bf16.bf16.f32 "
        "{%0,%1,%2,%3}, {%4,%5,%6,%7}, {%8,%9}, {%0,%1,%2,%3};"
        : "+f"(c[0]), "+f"(c[1]), "+f"(c[2]), "+f"(c[3])
        : "r"(a[0]), "r"(a[1]), "r"(a[2]), "r"(a[3]), "r"(b[0]), "r"(b[1]));
}

#define CP16(dst, src) \
    asm volatile("cp.async.cg.shared.global [%0], [%1], 16;" \
                 :: "r"(dst), "l"(src) : "memory")
#define CP_COMMIT() asm volatile("cp.async.commit_group;" ::: "memory")
#define CP_WAIT0()  asm volatile("cp.async.wait_group 0;" ::: "memory")

// ============================================================================
// tensor-core GEMM v3.1: bf16 hi/lo operands, cp.async double-buffer pipeline,
// split-K via blockIdx.z (K = per-split chunk; C += z*zstrC; use beta=0).
// C[M,N] = (Ah+Al)[M,K] @ (Bh+Bl)[N,K]^T (3-term) (+bias)(+rowvec)(+beta*C)
// Block 128x128, BK=32, 8 warps (2x4). XOR-swizzled 64B rows. 2 CTAs/SM.
// ============================================================================
#define TGV_REGION 8192
#define TGV_STAGE  32768
#define TGV_SMEM   65536

__global__ __launch_bounds__(256, 2)
void tgemm_k(const __nv_bfloat16* __restrict__ Ah, const __nv_bfloat16* __restrict__ Al,
             int lda,
             const __nv_bfloat16* __restrict__ Bh, const __nv_bfloat16* __restrict__ Bl,
             int ldb,
             float* __restrict__ C, int ldc,
             const float* __restrict__ bias,
             const float* __restrict__ rowvec,
             int K, int beta, int zstrC)
{
    extern __shared__ __align__(16) char smem[];
    const uint32_t sb = smem_u32(smem);
    const int tid  = threadIdx.x;
    const int wid  = tid >> 5;
    const int lane = tid & 31;
    const int m0 = blockIdx.y * 128;
    const int n0 = blockIdx.x * 128;
    const int kz = blockIdx.z * K;          // split-K offset
    C += (size_t)blockIdx.z * zstrC;
    const int wm = wid >> 2;
    const int wn = wid & 3;

    float acc[4][4][4];
#pragma unroll
    for (int i = 0; i < 4; i++)
#pragma unroll
        for (int j = 0; j < 4; j++)
#pragma unroll
            for (int k = 0; k < 4; k++) acc[i][j][k] = 0.f;

    // ---- cp.async staging geometry ----
    const int s_row = tid >> 1;
    const int c0    = (tid & 1) * 2;
    const int ssw   = (s_row >> 1) & 3;
    const uint32_t d0 = (uint32_t)(s_row * 64 + ((c0     ^ ssw) * 16));
    const uint32_t d1 = (uint32_t)(s_row * 64 + (((c0+1) ^ ssw) * 16));
    const __nv_bfloat16* Ah_s = Ah + (size_t)(m0 + s_row) * lda + kz + c0 * 8;
    const __nv_bfloat16* Al_s = Al + (size_t)(m0 + s_row) * lda + kz + c0 * 8;
    const __nv_bfloat16* Bh_s = Bh + (size_t)(n0 + s_row) * ldb + kz + c0 * 8;
    const __nv_bfloat16* Bl_s = Bl + (size_t)(n0 + s_row) * ldb + kz + c0 * 8;

    // ---- ldmatrix relative offsets (XOR swizzle baked in) ----
    const int q  = lane >> 3;
    const int r8 = lane & 7;
    const int qh = q >> 1;
    const int qb = q & 1;
    uint32_t a_rel[4][2], b_rel[2][2];
#pragma unroll
    for (int mt = 0; mt < 4; mt++) {
        const int ar = wm * 64 + mt * 16 + (q & 1) * 8 + r8;
        const int sw = (ar >> 1) & 3;
#pragma unroll
        for (int ks = 0; ks < 2; ks++)
            a_rel[mt][ks] = (uint32_t)(ar * 64 + (((ks * 2 + qh) ^ sw) * 16));
    }
#pragma unroll
    for (int h = 0; h < 2; h++) {
        const int br = wn * 32 + h * 16 + (q >> 1) * 8 + r8;
        const int sw = (br >> 1) & 3;
#pragma unroll
        for (int ks = 0; ks < 2; ks++)
            b_rel[h][ks] = (uint32_t)(2 * TGV_REGION + br * 64 + (((ks * 2 + qb) ^ sw) * 16));
    }

    const int chunks = K >> 5;

    // prologue: stage chunk 0 into buffer 0
    {
        const uint32_t s0 = sb;
        CP16(s0 + d0, Ah_s);                    CP16(s0 + d1, Ah_s + 8);
        CP16(s0 + TGV_REGION + d0, Al_s);       CP16(s0 + TGV_REGION + d1, Al_s + 8);
        CP16(s0 + 2*TGV_REGION + d0, Bh_s);     CP16(s0 + 2*TGV_REGION + d1, Bh_s + 8);
        CP16(s0 + 3*TGV_REGION + d0, Bl_s);     CP16(s0 + 3*TGV_REGION + d1, Bl_s + 8);
        CP_COMMIT();
    }

    for (int c = 0; c < chunks; c++) {
        CP_WAIT0();
        __syncthreads();
        const uint32_t sbuf = sb + (uint32_t)(c & 1) * TGV_STAGE;
        if (c + 1 < chunks) {
            const uint32_t sn = sb + (uint32_t)((c + 1) & 1) * TGV_STAGE;
            const int ko = (c + 1) * 32;
            CP16(sn + d0, Ah_s + ko);                CP16(sn + d1, Ah_s + ko + 8);
            CP16(sn + TGV_REGION + d0, Al_s + ko);   CP16(sn + TGV_REGION + d1, Al_s + ko + 8);
            CP16(sn + 2*TGV_REGION + d0, Bh_s + ko); CP16(sn + 2*TGV_REGION + d1, Bh_s + ko + 8);
            CP16(sn + 3*TGV_REGION + d0, Bl_s + ko); CP16(sn + 3*TGV_REGION + d1, Bl_s + ko + 8);
            CP_COMMIT();
        }

#pragma unroll
        for (int ks = 0; ks < 2; ks++) {
            uint32_t bh[2][4], bl[2][4];
            ldsm4(bh[0], sbuf + b_rel[0][ks]);
            ldsm4(bh[1], sbuf + b_rel[1][ks]);
            ldsm4(bl[0], sbuf + b_rel[0][ks] + TGV_REGION);
            ldsm4(bl[1], sbuf + b_rel[1][ks] + TGV_REGION);
#pragma unroll
            for (int mt = 0; mt < 4; mt++) {
                uint32_t ah[4], al[4];
                ldsm4(ah, sbuf + a_rel[mt][ks]);
                ldsm4(al, sbuf + a_rel[mt][ks] + TGV_REGION);
#pragma unroll
                for (int nt = 0; nt < 4; nt++) {
                    const uint32_t* bhp = &bh[nt >> 1][(nt & 1) * 2];
                    const uint32_t* blp = &bl[nt >> 1][(nt & 1) * 2];
                    mma_bf16(acc[mt][nt], ah, bhp);
                    mma_bf16(acc[mt][nt], ah, blp);
                    mma_bf16(acc[mt][nt], al, bhp);
                }
            }
        }
    }

    // epilogue
    const int er = lane >> 2;
    const int ec = (lane & 3) * 2;
    const int colbase = n0 + wn * 32 + ec;
#pragma unroll
    for (int mt = 0; mt < 4; mt++) {
#pragma unroll
        for (int half = 0; half < 2; half++) {
            const int row = m0 + wm * 64 + mt * 16 + er + half * 8;
            float* cp = C + (size_t)row * ldc + colbase;
            const float* rv = rowvec ? rowvec + (size_t)(row >> 10) * ldc + colbase
                                     : nullptr;
#pragma unroll
            for (int nt = 0; nt < 4; nt++) {
                float v0 = acc[mt][nt][half * 2 + 0];
                float v1 = acc[mt][nt][half * 2 + 1];
                const int co = nt * 8;
                if (bias) { v0 += bias[colbase + co]; v1 += bias[colbase + co + 1]; }
                if (rv)   { v0 += rv[co];             v1 += rv[co + 1]; }
                if (beta) { v0 += cp[co];             v1 += cp[co + 1]; }
                *(float2*)(cp + co) = make_float2(v0, v1);
            }
        }
    }
}

// 4-way split-K reduce over cols 0..63 only (dtp|B|C); ld = 128 floats.
__global__ void reduce4_k(const float* __restrict__ p, float* __restrict__ out)
{
    const int i = blockIdx.x * 256 + threadIdx.x;   // over ROWS*64/4 float4s
    const int row = i >> 4;
    const int c4  = i & 15;
    const int o   = row * 32 + c4;                  // float4 index, ld=128
    const int STR4 = ROWS * 32;                     // float4 stride per split
    float4 a = ((const float4*)p)[o];
    float4 b = ((const float4*)p)[o + STR4];
    float4 c = ((const float4*)p)[o + 2 * STR4];
    float4 d = ((const float4*)p)[o + 3 * STR4];
    float4 r;
    r.x = (a.x + b.x) + (c.x + d.x);
    r.y = (a.y + b.y) + (c.y + d.y);
    r.z = (a.z + b.z) + (c.z + d.z);
    r.w = (a.w + b.w) + (c.w + d.w);
    ((float4*)out)[o] = r;
}

// ---------------- weight prep ----------------
__global__ void weights_conv_k(const float* __restrict__ w1,
                               const float* __restrict__ w2,
                               const float* __restrict__ ipw,
                               const float* __restrict__ xpw,
                               const float* __restrict__ opw,
                               __nv_bfloat16* __restrict__ wh,
                               __nv_bfloat16* __restrict__ wl)
{
    const int idx = blockIdx.x * 256 + threadIdx.x;
    float v;
    if (idx < OFF_W2)       v = w1[idx];
    else if (idx < OFF_IP)  v = w2[idx - OFF_W2];
    else if (idx < OFF_XP)  v = ipw[idx - OFF_IP];
    else if (idx < OFF_OP) {
        const int l = idx - OFF_XP;
        const int layer = l / SZ_XP;
        const int r = l % SZ_XP;
        const int row = r >> 10, col = r & 1023;
        v = (row < 64) ? xpw[layer * 64 * 1024 + row * 1024 + col] : 0.f;
    } else                  v = opw[idx - OFF_OP];
    __nv_bfloat16 h, l;
    split1(v, h, l);
    wh[idx] = h; wl[idx] = l;
}

__global__ void transpose_wup_k(const float* __restrict__ in,
                                __nv_bfloat16* __restrict__ oh,
                                __nv_bfloat16* __restrict__ ol)
{
    __shared__ float t[32][33];
    const int bx = blockIdx.x, by = blockIdx.y;
    {
        const int x = bx * 32 + threadIdx.x;
        const int y = by * 32 + threadIdx.y;
#pragma unroll
        for (int i = 0; i < 32; i += 8)
            t[threadIdx.y + i][threadIdx.x] = in[(size_t)(y + i) * 1024 + x];
    }
    __syncthreads();
    {
        const int x = by * 32 + threadIdx.x;
        const int y = bx * 32 + threadIdx.y;
#pragma unroll
        for (int i = 0; i < 32; i += 8) {
            __nv_bfloat16 h, l;
            split1(t[threadIdx.x][threadIdx.y + i], h, l);
            oh[(size_t)(y + i) * 512 + x] = h;
            ol[(size_t)(y + i) * 512 + x] = l;
        }
    }
}

// motion convert (dense, ld 512)
__global__ void convert_pair_k(const float* __restrict__ src,
                               __nv_bfloat16* __restrict__ h,
                               __nv_bfloat16* __restrict__ l)
{
    const int i = blockIdx.x * 256 + threadIdx.x;
    float4 v = ((const float4*)src)[i];
    uint32_t h01, h23, l01, l23;
    split4(v, h01, h23, l01, l23);
    ((uint2*)h)[i] = make_uint2(h01, h23);
    ((uint2*)l)[i] = make_uint2(l01, l23);
}

// skip convert into cat buffer cols 512..1023 (ld 1024)
__global__ void convert_skip_k(const float* __restrict__ src,
                               __nv_bfloat16* __restrict__ h,
                               __nv_bfloat16* __restrict__ l)
{
    const int i = blockIdx.x * 256 + threadIdx.x;   // over ROWS*512/4
    const int row  = i >> 7;
    const int col4 = i & 127;
    float4 v = ((const float4*)src)[i];
    uint32_t h01, h23, l01, l23;
    split4(v, h01, h23, l01, l23);
    const int o = row * 256 + 128 + col4;           // uint2 units, ld=1024 elems
    ((uint2*)h)[o] = make_uint2(h01, h23);
    ((uint2*)l)[o] = make_uint2(l01, l23);
}

// ---------------- layernorm -> f32 out (final) ----------------
__global__ void layernorm_k(const float* __restrict__ x,
                            const float* __restrict__ w,
                            const float* __restrict__ b,
                            float* __restrict__ out)
{
    const int row = blockIdx.x;
    const int tid = threadIdx.x;
    float4 v = ((const float4*)(x + (size_t)row * 512))[tid];
    float s  = v.x + v.y + v.z + v.w;
    float sq = v.x * v.x + v.y * v.y + v.z * v.z + v.w * v.w;
#pragma unroll
    for (int o = 16; o > 0; o >>= 1) {
        s  += __shfl_xor_sync(0xffffffffu, s,  o);
        sq += __shfl_xor_sync(0xffffffffu, sq, o);
    }
    __shared__ float ss[4], ssq[4];
    const int wid = tid >> 5;
    if ((tid & 31) == 0) { ss[wid] = s; ssq[wid] = sq; }
    __syncthreads();
    s  = ss[0]  + ss[1]  + ss[2]  + ss[3];
    sq = ssq[0] + ssq[1] + ssq[2] + ssq[3];
    const float m   = s  * (1.f / 512.f);
    const float var = sq * (1.f / 512.f) - m * m;
    const float inv = rsqrtf(var + 1e-5f);
    float4 wv = ((const float4*)w)[tid];
    float4 bv = ((const float4*)b)[tid];
    float4 o4;
    o4.x = (v.x - m) * inv * wv.x + bv.x;
    o4.y = (v.y - m) * inv * wv.y + bv.y;
    o4.z = (v.z - m) * inv * wv.z + bv.z;
    o4.w = (v.w - m) * inv * wv.w + bv.w;
    ((float4*)(out + (size_t)row * 512))[tid] = o4;
}

// ---------------- layernorm -> bf16 hi/lo pair ----------------
__global__ void layernorm_bf_k(const float* __restrict__ x,
                               const float* __restrict__ w,
                               const float* __restrict__ b,
                               __nv_bfloat16* __restrict__ oh,
                               __nv_bfloat16* __restrict__ ol)
{
    const int row = blockIdx.x;
    const int tid = threadIdx.x;
    float4 v = ((const float4*)(x + (size_t)row * 512))[tid];
    float s  = v.x + v.y + v.z + v.w;
    float sq = v.x * v.x + v.y * v.y + v.z * v.z + v.w * v.w;
#pragma unroll
    for (int o = 16; o > 0; o >>= 1) {
        s  += __shfl_xor_sync(0xffffffffu, s,  o);
        sq += __shfl_xor_sync(0xffffffffu, sq, o);
    }
    __shared__ float ss[4], ssq[4];
    const int wid = tid >> 5;
    if ((tid & 31) == 0) { ss[wid] = s; ssq[wid] = sq; }
    __syncthreads();
    s  = ss[0]  + ss[1]  + ss[2]  + ss[3];
    sq = ssq[0] + ssq[1] + ssq[2] + ssq[3];
    const float m   = s  * (1.f / 512.f);
    const float var = sq * (1.f / 512.f) - m * m;
    const float inv = rsqrtf(var + 1e-5f);
    float4 wv = ((const float4*)w)[tid];
    float4 bv = ((const float4*)b)[tid];
    float4 o4;
    o4.x = (v.x - m) * inv * wv.x + bv.x;
    o4.y = (v.y - m) * inv * wv.y + bv.y;
    o4.z = (v.z - m) * inv * wv.z + bv.z;
    o4.w = (v.w - m) * inv * wv.w + bv.w;
    uint32_t h01, h23, l01, l23;
    split4(o4, h01, h23, l01, l23);
    ((uint2*)(oh + (size_t)row * 512))[tid] = make_uint2(h01, h23);
    ((uint2*)(ol + (size_t)row * 512))[tid] = make_uint2(l01, l23);
}

// ---------------- rmsnorm + silu -> bf16 hi/lo pair ----------------
__global__ void rmsnorm_silu_k(const float* __restrict__ x,
                               const float* __restrict__ w,
                               __nv_bfloat16* __restrict__ oh,
                               __nv_bfloat16* __restrict__ ol)
{
    const int row = blockIdx.x;
    const int tid = threadIdx.x;
    float4 v = ((const float4*)(x + (size_t)row * 512))[tid];
    float sq = v.x * v.x + v.y * v.y + v.z * v.z + v.w * v.w;
#pragma unroll
    for (int o = 16; o > 0; o >>= 1) sq += __shfl_xor_sync(0xffffffffu, sq, o);
    __shared__ float ssq[4];
    const int wid = tid >> 5;
    if ((tid & 31) == 0) ssq[wid] = sq;
    __syncthreads();
    sq = ssq[0] + ssq[1] + ssq[2] + ssq[3];
    const float inv = rsqrtf(sq * (1.f / 512.f) + 1e-5f);
    float4 wv = ((const float4*)w)[tid];
    float4 o4;
    float a;
    a = v.x * inv * wv.x; o4.x = siluf(a);
    a = v.y * inv * wv.y; o4.y = siluf(a);
    a = v.z * inv * wv.z; o4.z = siluf(a);
    a = v.w * inv * wv.w; o4.w = siluf(a);
    uint32_t h01, h23, l01, l23;
    split4(o4, h01, h23, l01, l23);
    ((uint2*)(oh + (size_t)row * 512))[tid] = make_uint2(h01, h23);
    ((uint2*)(ol + (size_t)row * 512))[tid] = make_uint2(l01, l23);
}

// ---------------- up rearrange -> cat buffer cols 0..511 (+b_up) ----------------
__global__ void up_rearrange_k(const float* __restrict__ up_tmp,
                               const float* __restrict__ b_up,
                               __nv_bfloat16* __restrict__ oh,
                               __nv_bfloat16* __restrict__ ol)
{
    const int idx  = blockIdx.x * blockDim.x + threadIdx.x;   // ROWS*512
    const int o    = idx & 511;
    const int orow = idx >> 9;
    const int b    = orow >> 10;
    const int t    = orow & 1023;
    const int l    = t >> 1;
    const int k    = t & 1;
    const float v = up_tmp[(size_t)(b * 512 + l) * 1024 + o * 2 + k] + b_up[o];
    __nv_bfloat16 h, lo;
    split1(v, h, lo);
    const size_t oo = (size_t)orow * 1024 + o;   // cat buffer, ld 1024
    oh[oo] = h; ol[oo] = lo;
}

// ---------------- causal depthwise conv(4) + bias + silu ----------------
__global__ void conv_silu_k(const float* __restrict__ xz,
                            const float* __restrict__ cw,
                            const float* __restrict__ cb,
                            float* __restrict__ xc,
                            __nv_bfloat16* __restrict__ oh,
                            __nv_bfloat16* __restrict__ ol)
{
    const int idx = blockIdx.x * blockDim.x + threadIdx.x;
    const int d   = idx & 1023;
    const int row = idx >> 10;
    const int t   = row & 1023;
    float acc = cb[d];
#pragma unroll
    for (int j = 0; j < 4; j++) {
        const int tt = t - 3 + j;
        if (tt >= 0)
            acc = fmaf(cw[d * 4 + j], xz[(size_t)(row - 3 + j) * 2048 + d], acc);
    }
    const float v = siluf(acc);
    xc[idx] = v;
    __nv_bfloat16 h, l;
    split1(v, h, l);
    oh[idx] = h; ol[idx] = l;
}

// ---------------- selective scan with fused dt_proj + softplus ----------------
// 4 threads per channel (quarter-split of 16 states). dt computed in-kernel:
// dt[t,d] = softplus(dot(xdbc[t,0:32], dtw[d,:]) + dtb[d]); each thread holds
// 8 dtw weights, 2 shfls assemble the dot across the quad.
__global__ __launch_bounds__(128)
void scan_k(const float* __restrict__ xc,      // u [ROWS,1024]
            const float* __restrict__ xz,      // z at col 1024+d, ld 2048
            const float* __restrict__ xdbc,    // [ROWS,128]: dtp(32)|B(16)|C(16)|pad
            const float* __restrict__ dtw,     // [1024,32] this layer
            const float* __restrict__ dtb,     // [1024]
            const float* __restrict__ A_log,
            const float* __restrict__ Dp,
            __nv_bfloat16* __restrict__ yh,
            __nv_bfloat16* __restrict__ yl)
{
    __shared__ __align__(16) float bc_s[32][68];   // 64 cols + 4 pad (bank rotate)

    const int tid     = threadIdx.x;         // 128
    const int quarter = tid & 3;
    const int dloc    = tid >> 2;             // 0..31
    const int b       = blockIdx.x >> 5;      // 0..7
    const int d       = (blockIdx.x & 31) * 32 + dloc;
    const int n0      = quarter * 4;

    float A2[4], h[4];
#pragma unroll
    for (int j = 0; j < 4; j++) {
        A2[j] = -__expf(A_log[d * 16 + n0 + j]) * 1.44269504f;
        h[j]  = 0.f;
    }
    const float Dd = Dp[d];
    const float dtbias = dtb[d];

    // dtw chunk: this thread covers weights quarter*8 .. +7
    float w8[8];
    {
        const float* wp = dtw + d * 32 + quarter * 8;
        *(float4*)&w8[0] = *(const float4*)wp;
        *(float4*)&w8[4] = *(const float4*)(wp + 4);
    }

    const float* up  = xc   + (size_t)b * 1024 * 1024 + d;
    const float* zp  = xz   + (size_t)b * 1024 * 2048 + 1024 + d;
    const float* bcb = xdbc + (size_t)b * 1024 * 128;   // cols 0..63 staged
    __nv_bfloat16* yhp = yh + (size_t)b * 1024 * 1024 + d;
    __nv_bfloat16* ylp = yl + (size_t)b * 1024 * 1024 + d;

    const int st_t = tid >> 2;         // 0..31
    const int st_c = (tid & 3) * 16;   // 0,16,32,48

    for (int c = 0; c < 32; c++) {
        __syncthreads();
        {
            const float* src = bcb + (size_t)(c * 32 + st_t) * 128 + st_c;
            *(float4*)&bc_s[st_t][st_c]      = *(const float4*)src;
            *(float4*)&bc_s[st_t][st_c + 4]  = *(const float4*)(src + 4);
            *(float4*)&bc_s[st_t][st_c + 8]  = *(const float4*)(src + 8);
            *(float4*)&bc_s[st_t][st_c + 12] = *(const float4*)(src + 12);
        }
        __syncthreads();

#pragma unroll
        for (int s = 0; s < 4; s++) {
            const int tbase = c * 32 + s * 8;
            float u8[8], z8[8];
#pragma unroll
            for (int j = 0; j < 8; j++) {
                u8[j] = up[(size_t)(tbase + j) * 1024];
                z8[j] = zp[(size_t)(tbase + j) * 2048];
            }
#pragma unroll
            for (int j = 0; j < 8; j++) {
                const int tt = s * 8 + j;
                // dt = softplus(dot(dtp, dtw[d]) + dtb[d])
                float pd = 0.f;
#pragma unroll
                for (int k = 0; k < 8; k++)
                    pd = fmaf(bc_s[tt][quarter * 8 + k], w8[k], pd);
                pd += __shfl_xor_sync(0xffffffffu, pd, 1);
                pd += __shfl_xor_sync(0xffffffffu, pd, 2);
                const float dtv = softplusf(pd + dtbias);

                float Bv[4], Cv[4];
                *(float4*)&Bv[0] = *(const float4*)&bc_s[tt][32 + n0];
                *(float4*)&Cv[0] = *(const float4*)&bc_s[tt][48 + n0];
                const float u  = u8[j];
                const float du = dtv * u;
                float ya = 0.f, yb2 = 0.f;
#pragma unroll
                for (int n = 0; n < 4; n++) {
                    const float dA = exp2f(dtv * A2[n]);
                    h[n] = fmaf(dA, h[n], du * Bv[n]);
                    if (n & 1) yb2 = fmaf(h[n], Cv[n], yb2);
                    else       ya  = fmaf(h[n], Cv[n], ya);
                }
                float ysum = ya + yb2;
                ysum += __shfl_xor_sync(0xffffffffu, ysum, 1);
                ysum += __shfl_xor_sync(0xffffffffu, ysum, 2);
                if (quarter == 0) {
                    const float w = (ysum + u * Dd) * siluf(z8[j]);
                    __nv_bfloat16 wh, wl;
                    split1(w, wh, wl);
                    yhp[(size_t)(tbase + j) * 1024] = wh;
                    ylp[(size_t)(tbase + j) * 1024] = wl;
                }
            }
        }
    }
}

// ---------------- launcher ----------------
extern "C" void kernel_launch(void* const* d_in, const int* in_sizes, int n_in,
                              void* d_out, int out_size)
{
    (void)in_sizes; (void)n_in; (void)out_size;

    const float* motion     = (const float*)d_in[0];
    const float* skip       = (const float*)d_in[1];
    const float* embed      = (const float*)d_in[2];
    const float* w_up       = (const float*)d_in[3];
    const float* b_up       = (const float*)d_in[4];
    const float* w1         = (const float*)d_in[5];
    const float* b1         = (const float*)d_in[6];
    const float* rms_w      = (const float*)d_in[7];
    const float* w2         = (const float*)d_in[8];
    const float* b2         = (const float*)d_in[9];
    const float* ln_w       = (const float*)d_in[10];
    const float* ln_b       = (const float*)d_in[11];
    const float* in_proj_w  = (const float*)d_in[12];
    const float* conv_w     = (const float*)d_in[13];
    const float* conv_b     = (const float*)d_in[14];
    const float* x_proj_w   = (const float*)d_in[15];
    const float* dt_proj_w  = (const float*)d_in[16];
    const float* dt_proj_b  = (const float*)d_in[17];
    const float* A_log      = (const float*)d_in[18];
    const float* D_param    = (const float*)d_in[19];
    const float* out_proj_w = (const float*)d_in[20];
    const float* out_proj_b = (const float*)d_in[21];
    const float* norm_f_w   = (const float*)d_in[22];
    const float* norm_f_b   = (const float*)d_in[23];
    float* out = (float*)d_out;

    float *up_tmp, *h, *x, *xz, *xc, *xdbc, *xpart;
    cudaGetSymbolAddress((void**)&up_tmp, g_up_tmp);
    cudaGetSymbolAddress((void**)&h,      g_h);
    cudaGetSymbolAddress((void**)&x,      g_x);
    cudaGetSymbolAddress((void**)&xz,     g_xz);
    cudaGetSymbolAddress((void**)&xc,     g_xc);
    cudaGetSymbolAddress((void**)&xdbc,   g_xdbc);
    cudaGetSymbolAddress((void**)&xpart,  g_xpart);

    __nv_bfloat16 *mo_h, *mo_l, *cat_h, *cat_l, *hh, *hl;
    __nv_bfloat16 *ln_h, *ln_l, *xc_h, *xc_l, *y_h, *y_l;
    __nv_bfloat16 *wupT_h, *wupT_l, *wb_h, *wb_l;
    cudaGetSymbolAddress((void**)&mo_h, g_mo_h);   cudaGetSymbolAddress((void**)&mo_l, g_mo_l);
    cudaGetSymbolAddress((void**)&cat_h, g_cat_h); cudaGetSymbolAddress((void**)&cat_l, g_cat_l);
    cudaGetSymbolAddress((void**)&hh,   g_hh);     cudaGetSymbolAddress((void**)&hl,   g_hl);
    cudaGetSymbolAddress((void**)&ln_h, g_lnh);    cudaGetSymbolAddress((void**)&ln_l, g_lnl);
    cudaGetSymbolAddress((void**)&xc_h, g_xch);    cudaGetSymbolAddress((void**)&xc_l, g_xcl);
    cudaGetSymbolAddress((void**)&y_h,  g_yh);     cudaGetSymbolAddress((void**)&y_l,  g_yl);
    cudaGetSymbolAddress((void**)&wupT_h, g_wupT_h); cudaGetSymbolAddress((void**)&wupT_l, g_wupT_l);
    cudaGetSymbolAddress((void**)&wb_h, g_wb_h);   cudaGetSymbolAddress((void**)&wb_l, g_wb_l);

    cudaFuncSetAttribute(tgemm_k, cudaFuncAttributeMaxDynamicSharedMemorySize,
                         TGV_SMEM);

    // ---- weight + input conversion ----
    weights_conv_k<<<WB_TOTAL / 256, 256>>>(w1, w2, in_proj_w, x_proj_w,
                                            out_proj_w, wb_h, wb_l);
    transpose_wup_k<<<dim3(32, 16), dim3(32, 8)>>>(w_up, wupT_h, wupT_l);
    convert_pair_k<<<(4096 * 512 / 4) / 256, 256>>>(motion, mo_h, mo_l);
    convert_skip_k<<<(ROWS * 512 / 4) / 256, 256>>>(skip, cat_h, cat_l);

    // 1) up = motion @ w_up
    tgemm_k<<<dim3(8, 32), 256, TGV_SMEM>>>(
        mo_h, mo_l, 512, wupT_h, wupT_l, 512, up_tmp, 1024,
        nullptr, nullptr, 512, 0, 0);

    // 2) rearrange + b_up -> cat cols 0..511
    up_rearrange_k<<<(ROWS * 512) / 256, 256>>>(up_tmp, b_up, cat_h, cat_l);

    // 3) h = [up|skip] @ w1^T + b1   (single K=1024 GEMM)
    tgemm_k<<<dim3(4, 64), 256, TGV_SMEM>>>(
        cat_h, cat_l, 1024, wb_h + OFF_W1, wb_l + OFF_W1, 1024, h, 512,
        b1, nullptr, 1024, 0, 0);

    // 4) silu(rmsnorm(h)) -> bf16 pair
    rmsnorm_silu_k<<<ROWS, 128>>>(h, rms_w, hh, hl);

    // 5) x = h @ w2^T + b2 + embed[b]
    tgemm_k<<<dim3(4, 64), 256, TGV_SMEM>>>(
        hh, hl, 512, wb_h + OFF_W2, wb_l + OFF_W2, 512, x, 512,
        b2, embed, 512, 0, 0);

    // 6) mamba layers
    for (int i = 0; i < NDEPTH; i++) {
        layernorm_bf_k<<<ROWS, 128>>>(x, ln_w + i * 512, ln_b + i * 512, ln_h, ln_l);

        tgemm_k<<<dim3(16, 64), 256, TGV_SMEM>>>(
            ln_h, ln_l, 512,
            wb_h + OFF_IP + (size_t)i * SZ_IP, wb_l + OFF_IP + (size_t)i * SZ_IP, 512,
            xz, 2048, nullptr, nullptr, 512, 0, 0);

        conv_silu_k<<<(ROWS * DI) / 256, 256>>>(
            xz, conv_w + (size_t)i * 1024 * 4, conv_b + i * 1024, xc, xc_h, xc_l);

        // x_proj split-K=4
        tgemm_k<<<dim3(1, 64, 4), 256, TGV_SMEM>>>(
            xc_h, xc_l, 1024,
            wb_h + OFF_XP + (size_t)i * SZ_XP, wb_l + OFF_XP + (size_t)i * SZ_XP, 1024,
            xpart, 128, nullptr, nullptr, 256, 0, ROWS * 128);
        reduce4_k<<<(ROWS * 64 / 4) / 256, 256>>>(xpart, xdbc);

        // scan with fused dt_proj + softplus
        scan_k<<<256, 128>>>(
            xc, xz, xdbc,
            dt_proj_w + (size_t)i * 1024 * 32, dt_proj_b + i * 1024,
            A_log + (size_t)i * 1024 * 16, D_param + i * 1024, y_h, y_l);

        tgemm_k<<<dim3(4, 64), 256, TGV_SMEM>>>(
            y_h, y_l, 1024,
            wb_h + OFF_OP + (size_t)i * SZ_OP, wb_l + OFF_OP + (size_t)i * SZ_OP, 1024,
            x, 512, out_proj_b + i * 512, nullptr, 1024, 1, 0);
    }

    // 7) final layernorm -> output
    layernorm_k<<<ROWS, 128>>>(x, norm_f_w, norm_f_b, out);
}

// round 15
// speedup vs baseline: 1.0991x; 1.0991x over previous
#include <cuda_runtime.h>
#include <cuda_bf16.h>
#include <math.h>
#include <stdint.h>

// ---------------- problem constants ----------------
#define BB    8
#define LSEQ  1024            // 2*L_IN
#define ROWS  (BB*LSEQ)       // 8192 tokens
#define CC    512
#define DI    1024
#define DS    16
#define NDEPTH 4

// weight-pack offsets (elements) in the converted bf16 weight bank
#define OFF_W1   0
#define SZ_W1    (512*1024)
#define OFF_W2   (OFF_W1 + SZ_W1)
#define SZ_W2    (512*512)
#define OFF_IP   (OFF_W2 + SZ_W2)
#define SZ_IP    (2048*512)
#define OFF_XP   (OFF_IP + 4*SZ_IP)
#define SZ_XP    (128*1024)
#define OFF_OP   (OFF_XP + 4*SZ_XP)
#define SZ_OP    (512*1024)
#define WB_TOTAL (OFF_OP + 4*SZ_OP)   // 7,602,176

// ---------------- scratch (device globals; no allocs allowed) ----------------
__device__ float g_up_tmp[4096*1024];   // up GEMM raw output
__device__ float g_h    [ROWS*CC];      // h1 (pre-rmsnorm)
__device__ float g_x    [ROWS*CC];      // residual stream
__device__ float g_xz   [ROWS*2*DI];    // in_proj out (xc_raw | z)
__device__ float g_xc   [ROWS*DI];      // conv+silu out f32 (scan u)
__device__ float g_xdbc [ROWS*128];     // x_proj out (dtp|B|C|pad), ld=128
__device__ float g_xpart[4*ROWS*128];   // x_proj split-K partials

// bf16 hi/lo operand buffers
__device__ __align__(16) __nv_bfloat16 g_mo_h[4096*512],  g_mo_l[4096*512];
__device__ __align__(16) __nv_bfloat16 g_cat_h[ROWS*1024], g_cat_l[ROWS*1024]; // [up|skip]
__device__ __align__(16) __nv_bfloat16 g_hh[ROWS*512],    g_hl[ROWS*512];
__device__ __align__(16) __nv_bfloat16 g_lnh[ROWS*512],   g_lnl[ROWS*512];
__device__ __align__(16) __nv_bfloat16 g_xch[ROWS*1024],  g_xcl[ROWS*1024];
__device__ __align__(16) __nv_bfloat16 g_yh[ROWS*1024],   g_yl[ROWS*1024];
__device__ __align__(16) __nv_bfloat16 g_wupT_h[1024*512], g_wupT_l[1024*512];
__device__ __align__(16) __nv_bfloat16 g_wb_h[WB_TOTAL],   g_wb_l[WB_TOTAL];

// ---------------- helpers ----------------
__device__ __forceinline__ float softplusf(float x) {
    return (x > 20.f) ? x : log1pf(__expf(x));
}
__device__ __forceinline__ float siluf(float x) {
    return x / (1.f + __expf(-x));
}

__device__ __forceinline__ uint32_t smem_u32(const void* p) {
    uint32_t a;
    asm("{ .reg .u64 t; cvta.to.shared.u64 t, %1; cvt.u32.u64 %0, t; }"
        : "=r"(a) : "l"(p));
    return a;
}

__device__ __forceinline__ void split1(float v, __nv_bfloat16& h, __nv_bfloat16& l) {
    h = __float2bfloat16(v);
    l = __float2bfloat16(v - __bfloat162float(h));
}

// split f32x4 into bf16 hi / lo pairs (packed bf16x2 words, .x in low half)
__device__ __forceinline__ void split4(float4 v, uint32_t& h01, uint32_t& h23,
                                       uint32_t& l01, uint32_t& l23) {
    __nv_bfloat162 h0 = __float22bfloat162_rn(make_float2(v.x, v.y));
    __nv_bfloat162 h1 = __float22bfloat162_rn(make_float2(v.z, v.w));
    float2 f0 = __bfloat1622float2(h0), f1 = __bfloat1622float2(h1);
    __nv_bfloat162 l0 = __float22bfloat162_rn(make_float2(v.x - f0.x, v.y - f0.y));
    __nv_bfloat162 l1 = __float22bfloat162_rn(make_float2(v.z - f1.x, v.w - f1.y));
    h01 = *(uint32_t*)&h0; h23 = *(uint32_t*)&h1;
    l01 = *(uint32_t*)&l0; l23 = *(uint32_t*)&l1;
}

__device__ __forceinline__ void ldsm4(uint32_t* r, uint32_t addr) {
    asm volatile("ldmatrix.sync.aligned.m8n8.x4.shared.b16 {%0,%1,%2,%3}, [%4];"
        : "=r"(r[0]), "=r"(r[1]), "=r"(r[2]), "=r"(r[3]) : "r"(addr));
}

__device__ __forceinline__ void mma_bf16(float* c, const uint32_t* a, const uint32_t* b) {
    asm volatile("mma.sync.aligned.m16n8k16.row.col.f32.bf16.bf16.f32 "
        "{%0,%1,%2,%3}, {%4,%5,%6,%7}, {%8,%9}, {%0,%1,%2,%3};"
        : "+f"(c[0]), "+f"(c[1]), "+f"(c[2]), "+f"(c[3])
        : "r"(a[0]), "r"(a[1]), "r"(a[2]), "r"(a[3]), "r"(b[0]), "r"(b[1]));
}

#define CP16(dst, src) \
    asm volatile("cp.async.cg.shared.global [%0], [%1], 16;" \
                 :: "r"(dst), "l"(src) : "memory")
#define CP_COMMIT() asm volatile("cp.async.commit_group;" ::: "memory")
#define CP_WAIT1()  asm volatile("cp.async.wait_group 1;" ::: "memory")

// ============================================================================
// tensor-core GEMM v3.2: bf16 hi/lo operands, 3-stage cp.async pipeline,
// split-K via blockIdx.z (K = per-split chunk; C += z*zstrC; use beta=0).
// C[M,N] = (Ah+Al)[M,K] @ (Bh+Bl)[N,K]^T (3-term) (+bias)(+rowvec)(+beta*C)
// Block 128x128, BK=32, 8 warps (2x4). XOR-swizzled 64B rows.
// 3 stages x 32KB = 96KB dynamic smem; 2 CTAs/SM.
// ============================================================================
#define TGV_REGION 8192
#define TGV_STAGE  32768
#define TGV_SMEM   98304

__global__ __launch_bounds__(256, 2)
void tgemm_k(const __nv_bfloat16* __restrict__ Ah, const __nv_bfloat16* __restrict__ Al,
             int lda,
             const __nv_bfloat16* __restrict__ Bh, const __nv_bfloat16* __restrict__ Bl,
             int ldb,
             float* __restrict__ C, int ldc,
             const float* __restrict__ bias,
             const float* __restrict__ rowvec,
             int K, int beta, int zstrC)
{
    extern __shared__ __align__(16) char smem[];
    const uint32_t sb = smem_u32(smem);
    const int tid  = threadIdx.x;
    const int wid  = tid >> 5;
    const int lane = tid & 31;
    const int m0 = blockIdx.y * 128;
    const int n0 = blockIdx.x * 128;
    const int kz = blockIdx.z * K;          // split-K offset
    C += (size_t)blockIdx.z * zstrC;
    const int wm = wid >> 2;
    const int wn = wid & 3;

    float acc[4][4][4];
#pragma unroll
    for (int i = 0; i < 4; i++)
#pragma unroll
        for (int j = 0; j < 4; j++)
#pragma unroll
            for (int k = 0; k < 4; k++) acc[i][j][k] = 0.f;

    // ---- cp.async staging geometry ----
    const int s_row = tid >> 1;
    const int c0    = (tid & 1) * 2;
    const int ssw   = (s_row >> 1) & 3;
    const uint32_t d0 = (uint32_t)(s_row * 64 + ((c0     ^ ssw) * 16));
    const uint32_t d1 = (uint32_t)(s_row * 64 + (((c0+1) ^ ssw) * 16));
    const __nv_bfloat16* Ah_s = Ah + (size_t)(m0 + s_row) * lda + kz + c0 * 8;
    const __nv_bfloat16* Al_s = Al + (size_t)(m0 + s_row) * lda + kz + c0 * 8;
    const __nv_bfloat16* Bh_s = Bh + (size_t)(n0 + s_row) * ldb + kz + c0 * 8;
    const __nv_bfloat16* Bl_s = Bl + (size_t)(n0 + s_row) * ldb + kz + c0 * 8;

    // ---- ldmatrix relative offsets (XOR swizzle baked in) ----
    const int q  = lane >> 3;
    const int r8 = lane & 7;
    const int qh = q >> 1;
    const int qb = q & 1;
    uint32_t a_rel[4][2], b_rel[2][2];
#pragma unroll
    for (int mt = 0; mt < 4; mt++) {
        const int ar = wm * 64 + mt * 16 + (q & 1) * 8 + r8;
        const int sw = (ar >> 1) & 3;
#pragma unroll
        for (int ks = 0; ks < 2; ks++)
            a_rel[mt][ks] = (uint32_t)(ar * 64 + (((ks * 2 + qh) ^ sw) * 16));
    }
#pragma unroll
    for (int h = 0; h < 2; h++) {
        const int br = wn * 32 + h * 16 + (q >> 1) * 8 + r8;
        const int sw = (br >> 1) & 3;
#pragma unroll
        for (int ks = 0; ks < 2; ks++)
            b_rel[h][ks] = (uint32_t)(2 * TGV_REGION + br * 64 + (((ks * 2 + qb) ^ sw) * 16));
    }

    const int chunks = K >> 5;

    // prologue: stage chunks 0 and 1 into buffers 0 and 1 (separate groups)
#pragma unroll
    for (int p = 0; p < 2; p++) {
        const uint32_t s0 = sb + (uint32_t)p * TGV_STAGE;
        const int ko = p * 32;
        CP16(s0 + d0, Ah_s + ko);                CP16(s0 + d1, Ah_s + ko + 8);
        CP16(s0 + TGV_REGION + d0, Al_s + ko);   CP16(s0 + TGV_REGION + d1, Al_s + ko + 8);
        CP16(s0 + 2*TGV_REGION + d0, Bh_s + ko); CP16(s0 + 2*TGV_REGION + d1, Bh_s + ko + 8);
        CP16(s0 + 3*TGV_REGION + d0, Bl_s + ko); CP16(s0 + 3*TGV_REGION + d1, Bl_s + ko + 8);
        CP_COMMIT();
    }

    int buf = 0, pf = 2;
    for (int c = 0; c < chunks; c++) {
        CP_WAIT1();
        __syncthreads();
        const uint32_t sbuf = sb + (uint32_t)buf * TGV_STAGE;
        if (c + 2 < chunks) {
            const uint32_t sn = sb + (uint32_t)pf * TGV_STAGE;
            const int ko = (c + 2) * 32;
            CP16(sn + d0, Ah_s + ko);                CP16(sn + d1, Ah_s + ko + 8);
            CP16(sn + TGV_REGION + d0, Al_s + ko);   CP16(sn + TGV_REGION + d1, Al_s + ko + 8);
            CP16(sn + 2*TGV_REGION + d0, Bh_s + ko); CP16(sn + 2*TGV_REGION + d1, Bh_s + ko + 8);
            CP16(sn + 3*TGV_REGION + d0, Bl_s + ko); CP16(sn + 3*TGV_REGION + d1, Bl_s + ko + 8);
            CP_COMMIT();
        }

#pragma unroll
        for (int ks = 0; ks < 2; ks++) {
            uint32_t bh[2][4], bl[2][4];
            ldsm4(bh[0], sbuf + b_rel[0][ks]);
            ldsm4(bh[1], sbuf + b_rel[1][ks]);
            ldsm4(bl[0], sbuf + b_rel[0][ks] + TGV_REGION);
            ldsm4(bl[1], sbuf + b_rel[1][ks] + TGV_REGION);
#pragma unroll
            for (int mt = 0; mt < 4; mt++) {
                uint32_t ah[4], al[4];
                ldsm4(ah, sbuf + a_rel[mt][ks]);
                ldsm4(al, sbuf + a_rel[mt][ks] + TGV_REGION);
#pragma unroll
                for (int nt = 0; nt < 4; nt++) {
                    const uint32_t* bhp = &bh[nt >> 1][(nt & 1) * 2];
                    const uint32_t* blp = &bl[nt >> 1][(nt & 1) * 2];
                    mma_bf16(acc[mt][nt], ah, bhp);
                    mma_bf16(acc[mt][nt], ah, blp);
                    mma_bf16(acc[mt][nt], al, bhp);
                }
            }
        }
        buf = (buf == 2) ? 0 : buf + 1;
        pf  = (pf  == 2) ? 0 : pf  + 1;
    }

    // epilogue
    const int er = lane >> 2;
    const int ec = (lane & 3) * 2;
    const int colbase = n0 + wn * 32 + ec;
#pragma unroll
    for (int mt = 0; mt < 4; mt++) {
#pragma unroll
        for (int half = 0; half < 2; half++) {
            const int row = m0 + wm * 64 + mt * 16 + er + half * 8;
            float* cp = C + (size_t)row * ldc + colbase;
            const float* rv = rowvec ? rowvec + (size_t)(row >> 10) * ldc + colbase
                                     : nullptr;
#pragma unroll
            for (int nt = 0; nt < 4; nt++) {
                float v0 = acc[mt][nt][half * 2 + 0];
                float v1 = acc[mt][nt][half * 2 + 1];
                const int co = nt * 8;
                if (bias) { v0 += bias[colbase + co]; v1 += bias[colbase + co + 1]; }
                if (rv)   { v0 += rv[co];             v1 += rv[co + 1]; }
                if (beta) { v0 += cp[co];             v1 += cp[co + 1]; }
                *(float2*)(cp + co) = make_float2(v0, v1);
            }
        }
    }
}

// 4-way split-K reduce over cols 0..63 only (dtp|B|C); ld = 128 floats.
__global__ void reduce4_k(const float* __restrict__ p, float* __restrict__ out)
{
    const int i = blockIdx.x * 256 + threadIdx.x;   // over ROWS*64/4 float4s
    const int row = i >> 4;
    const int c4  = i & 15;
    const int o   = row * 32 + c4;                  // float4 index, ld=128
    const int STR4 = ROWS * 32;                     // float4 stride per split
    float4 a = ((const float4*)p)[o];
    float4 b = ((const float4*)p)[o + STR4];
    float4 c = ((const float4*)p)[o + 2 * STR4];
    float4 d = ((const float4*)p)[o + 3 * STR4];
    float4 r;
    r.x = (a.x + b.x) + (c.x + d.x);
    r.y = (a.y + b.y) + (c.y + d.y);
    r.z = (a.z + b.z) + (c.z + d.z);
    r.w = (a.w + b.w) + (c.w + d.w);
    ((float4*)out)[o] = r;
}

// ---------------- weight prep ----------------
__global__ void weights_conv_k(const float* __restrict__ w1,
                               const float* __restrict__ w2,
                               const float* __restrict__ ipw,
                               const float* __restrict__ xpw,
                               const float* __restrict__ opw,
                               __nv_bfloat16* __restrict__ wh,
                               __nv_bfloat16* __restrict__ wl)
{
    const int idx = blockIdx.x * 256 + threadIdx.x;
    float v;
    if (idx < OFF_W2)       v = w1[idx];
    else if (idx < OFF_IP)  v = w2[idx - OFF_W2];
    else if (idx < OFF_XP)  v = ipw[idx - OFF_IP];
    else if (idx < OFF_OP) {
        const int l = idx - OFF_XP;
        const int layer = l / SZ_XP;
        const int r = l % SZ_XP;
        const int row = r >> 10, col = r & 1023;
        v = (row < 64) ? xpw[layer * 64 * 1024 + row * 1024 + col] : 0.f;
    } else                  v = opw[idx - OFF_OP];
    __nv_bfloat16 h, l;
    split1(v, h, l);
    wh[idx] = h; wl[idx] = l;
}

__global__ void transpose_wup_k(const float* __restrict__ in,
                                __nv_bfloat16* __restrict__ oh,
                                __nv_bfloat16* __restrict__ ol)
{
    __shared__ float t[32][33];
    const int bx = blockIdx.x, by = blockIdx.y;
    {
        const int x = bx * 32 + threadIdx.x;
        const int y = by * 32 + threadIdx.y;
#pragma unroll
        for (int i = 0; i < 32; i += 8)
            t[threadIdx.y + i][threadIdx.x] = in[(size_t)(y + i) * 1024 + x];
    }
    __syncthreads();
    {
        const int x = by * 32 + threadIdx.x;
        const int y = bx * 32 + threadIdx.y;
#pragma unroll
        for (int i = 0; i < 32; i += 8) {
            __nv_bfloat16 h, l;
            split1(t[threadIdx.x][threadIdx.y + i], h, l);
            oh[(size_t)(y + i) * 512 + x] = h;
            ol[(size_t)(y + i) * 512 + x] = l;
        }
    }
}

// motion convert (dense, ld 512)
__global__ void convert_pair_k(const float* __restrict__ src,
                               __nv_bfloat16* __restrict__ h,
                               __nv_bfloat16* __restrict__ l)
{
    const int i = blockIdx.x * 256 + threadIdx.x;
    float4 v = ((const float4*)src)[i];
    uint32_t h01, h23, l01, l23;
    split4(v, h01, h23, l01, l23);
    ((uint2*)h)[i] = make_uint2(h01, h23);
    ((uint2*)l)[i] = make_uint2(l01, l23);
}

// skip convert into cat buffer cols 512..1023 (ld 1024)
__global__ void convert_skip_k(const float* __restrict__ src,
                               __nv_bfloat16* __restrict__ h,
                               __nv_bfloat16* __restrict__ l)
{
    const int i = blockIdx.x * 256 + threadIdx.x;   // over ROWS*512/4
    const int row  = i >> 7;
    const int col4 = i & 127;
    float4 v = ((const float4*)src)[i];
    uint32_t h01, h23, l01, l23;
    split4(v, h01, h23, l01, l23);
    const int o = row * 256 + 128 + col4;           // uint2 units, ld=1024 elems
    ((uint2*)h)[o] = make_uint2(h01, h23);
    ((uint2*)l)[o] = make_uint2(l01, l23);
}

// ---------------- layernorm -> f32 out (final) ----------------
__global__ void layernorm_k(const float* __restrict__ x,
                            const float* __restrict__ w,
                            const float* __restrict__ b,
                            float* __restrict__ out)
{
    const int row = blockIdx.x;
    const int tid = threadIdx.x;
    float4 v = ((const float4*)(x + (size_t)row * 512))[tid];
    float s  = v.x + v.y + v.z + v.w;
    float sq = v.x * v.x + v.y * v.y + v.z * v.z + v.w * v.w;
#pragma unroll
    for (int o = 16; o > 0; o >>= 1) {
        s  += __shfl_xor_sync(0xffffffffu, s,  o);
        sq += __shfl_xor_sync(0xffffffffu, sq, o);
    }
    __shared__ float ss[4], ssq[4];
    const int wid = tid >> 5;
    if ((tid & 31) == 0) { ss[wid] = s; ssq[wid] = sq; }
    __syncthreads();
    s  = ss[0]  + ss[1]  + ss[2]  + ss[3];
    sq = ssq[0] + ssq[1] + ssq[2] + ssq[3];
    const float m   = s  * (1.f / 512.f);
    const float var = sq * (1.f / 512.f) - m * m;
    const float inv = rsqrtf(var + 1e-5f);
    float4 wv = ((const float4*)w)[tid];
    float4 bv = ((const float4*)b)[tid];
    float4 o4;
    o4.x = (v.x - m) * inv * wv.x + bv.x;
    o4.y = (v.y - m) * inv * wv.y + bv.y;
    o4.z = (v.z - m) * inv * wv.z + bv.z;
    o4.w = (v.w - m) * inv * wv.w + bv.w;
    ((float4*)(out + (size_t)row * 512))[tid] = o4;
}

// ---------------- layernorm -> bf16 hi/lo pair ----------------
__global__ void layernorm_bf_k(const float* __restrict__ x,
                               const float* __restrict__ w,
                               const float* __restrict__ b,
                               __nv_bfloat16* __restrict__ oh,
                               __nv_bfloat16* __restrict__ ol)
{
    const int row = blockIdx.x;
    const int tid = threadIdx.x;
    float4 v = ((const float4*)(x + (size_t)row * 512))[tid];
    float s  = v.x + v.y + v.z + v.w;
    float sq = v.x * v.x + v.y * v.y + v.z * v.z + v.w * v.w;
#pragma unroll
    for (int o = 16; o > 0; o >>= 1) {
        s  += __shfl_xor_sync(0xffffffffu, s,  o);
        sq += __shfl_xor_sync(0xffffffffu, sq, o);
    }
    __shared__ float ss[4], ssq[4];
    const int wid = tid >> 5;
    if ((tid & 31) == 0) { ss[wid] = s; ssq[wid] = sq; }
    __syncthreads();
    s  = ss[0]  + ss[1]  + ss[2]  + ss[3];
    sq = ssq[0] + ssq[1] + ssq[2] + ssq[3];
    const float m   = s  * (1.f / 512.f);
    const float var = sq * (1.f / 512.f) - m * m;
    const float inv = rsqrtf(var + 1e-5f);
    float4 wv = ((const float4*)w)[tid];
    float4 bv = ((const float4*)b)[tid];
    float4 o4;
    o4.x = (v.x - m) * inv * wv.x + bv.x;
    o4.y = (v.y - m) * inv * wv.y + bv.y;
    o4.z = (v.z - m) * inv * wv.z + bv.z;
    o4.w = (v.w - m) * inv * wv.w + bv.w;
    uint32_t h01, h23, l01, l23;
    split4(o4, h01, h23, l01, l23);
    ((uint2*)(oh + (size_t)row * 512))[tid] = make_uint2(h01, h23);
    ((uint2*)(ol + (size_t)row * 512))[tid] = make_uint2(l01, l23);
}

// ---------------- rmsnorm + silu -> bf16 hi/lo pair ----------------
__global__ void rmsnorm_silu_k(const float* __restrict__ x,
                               const float* __restrict__ w,
                               __nv_bfloat16* __restrict__ oh,
                               __nv_bfloat16* __restrict__ ol)
{
    const int row = blockIdx.x;
    const int tid = threadIdx.x;
    float4 v = ((const float4*)(x + (size_t)row * 512))[tid];
    float sq = v.x * v.x + v.y * v.y + v.z * v.z + v.w * v.w;
#pragma unroll
    for (int o = 16; o > 0; o >>= 1) sq += __shfl_xor_sync(0xffffffffu, sq, o);
    __shared__ float ssq[4];
    const int wid = tid >> 5;
    if ((tid & 31) == 0) ssq[wid] = sq;
    __syncthreads();
    sq = ssq[0] + ssq[1] + ssq[2] + ssq[3];
    const float inv = rsqrtf(sq * (1.f / 512.f) + 1e-5f);
    float4 wv = ((const float4*)w)[tid];
    float4 o4;
    float a;
    a = v.x * inv * wv.x; o4.x = siluf(a);
    a = v.y * inv * wv.y; o4.y = siluf(a);
    a = v.z * inv * wv.z; o4.z = siluf(a);
    a = v.w * inv * wv.w; o4.w = siluf(a);
    uint32_t h01, h23, l01, l23;
    split4(o4, h01, h23, l01, l23);
    ((uint2*)(oh + (size_t)row * 512))[tid] = make_uint2(h01, h23);
    ((uint2*)(ol + (size_t)row * 512))[tid] = make_uint2(l01, l23);
}

// ---------------- up rearrange -> cat buffer cols 0..511 (+b_up) ----------------
__global__ void up_rearrange_k(const float* __restrict__ up_tmp,
                               const float* __restrict__ b_up,
                               __nv_bfloat16* __restrict__ oh,
                               __nv_bfloat16* __restrict__ ol)
{
    const int idx  = blockIdx.x * blockDim.x + threadIdx.x;   // ROWS*512
    const int o    = idx & 511;
    const int orow = idx >> 9;
    const int b    = orow >> 10;
    const int t    = orow & 1023;
    const int l    = t >> 1;
    const int k    = t & 1;
    const float v = up_tmp[(size_t)(b * 512 + l) * 1024 + o * 2 + k] + b_up[o];
    __nv_bfloat16 h, lo;
    split1(v, h, lo);
    const size_t oo = (size_t)orow * 1024 + o;   // cat buffer, ld 1024
    oh[oo] = h; ol[oo] = lo;
}

// ---------------- causal depthwise conv(4) + bias + silu ----------------
__global__ void conv_silu_k(const float* __restrict__ xz,
                            const float* __restrict__ cw,
                            const float* __restrict__ cb,
                            float* __restrict__ xc,
                            __nv_bfloat16* __restrict__ oh,
                            __nv_bfloat16* __restrict__ ol)
{
    const int idx = blockIdx.x * blockDim.x + threadIdx.x;
    const int d   = idx & 1023;
    const int row = idx >> 10;
    const int t   = row & 1023;
    float acc = cb[d];
#pragma unroll
    for (int j = 0; j < 4; j++) {
        const int tt = t - 3 + j;
        if (tt >= 0)
            acc = fmaf(cw[d * 4 + j], xz[(size_t)(row - 3 + j) * 2048 + d], acc);
    }
    const float v = siluf(acc);
    xc[idx] = v;
    __nv_bfloat16 h, l;
    split1(v, h, l);
    oh[idx] = h; ol[idx] = l;
}

// ---------------- selective scan, fused dt_proj (batched off critical path) ---
// 4 threads per channel (quarter-split of 16 states). Per 8-step batch, the
// quad computes dt[t] = softplus(dot(dtp[t], dtw[d]) + dtb[d]) via per-thread
// partial dots (8 weights each) + 2 batched shfl combines, all independent of
// the recurrence chain.
__global__ __launch_bounds__(128)
void scan_k(const float* __restrict__ xc,      // u [ROWS,1024]
            const float* __restrict__ xz,      // z at col 1024+d, ld 2048
            const float* __restrict__ xdbc,    // [ROWS,128]: dtp(32)|B(16)|C(16)|pad
            const float* __restrict__ dtw,     // [1024,32] this layer
            const float* __restrict__ dtb,     // [1024]
            const float* __restrict__ A_log,
            const float* __restrict__ Dp,
            __nv_bfloat16* __restrict__ yh,
            __nv_bfloat16* __restrict__ yl)
{
    __shared__ __align__(16) float bc_s[32][68];   // cols 0..63 staged (+pad)

    const int tid     = threadIdx.x;         // 128
    const int quarter = tid & 3;
    const int dloc    = tid >> 2;             // 0..31
    const int b       = blockIdx.x >> 5;      // 0..7
    const int d       = (blockIdx.x & 31) * 32 + dloc;
    const int n0      = quarter * 4;

    float A2[4], h[4];
#pragma unroll
    for (int j = 0; j < 4; j++) {
        A2[j] = -__expf(A_log[d * 16 + n0 + j]) * 1.44269504f;
        h[j]  = 0.f;
    }
    const float Dd = Dp[d];
    const float dtbias = dtb[d];

    // dtw chunk: this thread covers weights quarter*8 .. +7
    float w8[8];
    {
        const float* wp = dtw + d * 32 + quarter * 8;
        *(float4*)&w8[0] = *(const float4*)wp;
        *(float4*)&w8[4] = *(const float4*)(wp + 4);
    }

    const float* up  = xc   + (size_t)b * 1024 * 1024 + d;
    const float* zp  = xz   + (size_t)b * 1024 * 2048 + 1024 + d;
    const float* bcb = xdbc + (size_t)b * 1024 * 128;
    __nv_bfloat16* yhp = yh + (size_t)b * 1024 * 1024 + d;
    __nv_bfloat16* ylp = yl + (size_t)b * 1024 * 1024 + d;

    const int st_t = tid >> 2;         // 0..31
    const int st_c = (tid & 3) * 16;   // 0,16,32,48

    for (int c = 0; c < 32; c++) {
        __syncthreads();
        {
            const float* src = bcb + (size_t)(c * 32 + st_t) * 128 + st_c;
            *(float4*)&bc_s[st_t][st_c]      = *(const float4*)src;
            *(float4*)&bc_s[st_t][st_c + 4]  = *(const float4*)(src + 4);
            *(float4*)&bc_s[st_t][st_c + 8]  = *(const float4*)(src + 8);
            *(float4*)&bc_s[st_t][st_c + 12] = *(const float4*)(src + 12);
        }
        __syncthreads();

#pragma unroll
        for (int s = 0; s < 4; s++) {
            const int tbase = c * 32 + s * 8;
            // prefetch u, z for the batch
            float u8[8], z8[8];
#pragma unroll
            for (int j = 0; j < 8; j++) {
                u8[j] = up[(size_t)(tbase + j) * 1024];
                z8[j] = zp[(size_t)(tbase + j) * 2048];
            }
            // batched dt for 8 timesteps (independent of the h-chain)
            float pd[8];
#pragma unroll
            for (int j = 0; j < 8; j++) {
                const int tt = s * 8 + j;
                float a = 0.f;
#pragma unroll
                for (int k = 0; k < 8; k++)
                    a = fmaf(bc_s[tt][quarter * 8 + k], w8[k], a);
                pd[j] = a;
            }
#pragma unroll
            for (int j = 0; j < 8; j++) {
                pd[j] += __shfl_xor_sync(0xffffffffu, pd[j], 1);
                pd[j] += __shfl_xor_sync(0xffffffffu, pd[j], 2);
                pd[j] = softplusf(pd[j] + dtbias);
            }
            // serial recurrence
#pragma unroll
            for (int j = 0; j < 8; j++) {
                const int tt = s * 8 + j;
                float Bv[4], Cv[4];
                *(float4*)&Bv[0] = *(const float4*)&bc_s[tt][32 + n0];
                *(float4*)&Cv[0] = *(const float4*)&bc_s[tt][48 + n0];
                const float dtv = pd[j];
                const float u   = u8[j];
                const float du  = dtv * u;
                float ya = 0.f, yb2 = 0.f;
#pragma unroll
                for (int n = 0; n < 4; n++) {
                    const float dA = exp2f(dtv * A2[n]);
                    h[n] = fmaf(dA, h[n], du * Bv[n]);
                    if (n & 1) yb2 = fmaf(h[n], Cv[n], yb2);
                    else       ya  = fmaf(h[n], Cv[n], ya);
                }
                float ysum = ya + yb2;
                ysum += __shfl_xor_sync(0xffffffffu, ysum, 1);
                ysum += __shfl_xor_sync(0xffffffffu, ysum, 2);
                if (quarter == 0) {
                    const float w = (ysum + u * Dd) * siluf(z8[j]);
                    __nv_bfloat16 wh, wl;
                    split1(w, wh, wl);
                    yhp[(size_t)(tbase + j) * 1024] = wh;
                    ylp[(size_t)(tbase + j) * 1024] = wl;
                }
            }
        }
    }
}

// ---------------- launcher ----------------
extern "C" void kernel_launch(void* const* d_in, const int* in_sizes, int n_in,
                              void* d_out, int out_size)
{
    (void)in_sizes; (void)n_in; (void)out_size;

    const float* motion     = (const float*)d_in[0];
    const float* skip       = (const float*)d_in[1];
    const float* embed      = (const float*)d_in[2];
    const float* w_up       = (const float*)d_in[3];
    const float* b_up       = (const float*)d_in[4];
    const float* w1         = (const float*)d_in[5];
    const float* b1         = (const float*)d_in[6];
    const float* rms_w      = (const float*)d_in[7];
    const float* w2         = (const float*)d_in[8];
    const float* b2         = (const float*)d_in[9];
    const float* ln_w       = (const float*)d_in[10];
    const float* ln_b       = (const float*)d_in[11];
    const float* in_proj_w  = (const float*)d_in[12];
    const float* conv_w     = (const float*)d_in[13];
    const float* conv_b     = (const float*)d_in[14];
    const float* x_proj_w   = (const float*)d_in[15];
    const float* dt_proj_w  = (const float*)d_in[16];
    const float* dt_proj_b  = (const float*)d_in[17];
    const float* A_log      = (const float*)d_in[18];
    const float* D_param    = (const float*)d_in[19];
    const float* out_proj_w = (const float*)d_in[20];
    const float* out_proj_b = (const float*)d_in[21];
    const float* norm_f_w   = (const float*)d_in[22];
    const float* norm_f_b   = (const float*)d_in[23];
    float* out = (float*)d_out;

    float *up_tmp, *h, *x, *xz, *xc, *xdbc, *xpart;
    cudaGetSymbolAddress((void**)&up_tmp, g_up_tmp);
    cudaGetSymbolAddress((void**)&h,      g_h);
    cudaGetSymbolAddress((void**)&x,      g_x);
    cudaGetSymbolAddress((void**)&xz,     g_xz);
    cudaGetSymbolAddress((void**)&xc,     g_xc);
    cudaGetSymbolAddress((void**)&xdbc,   g_xdbc);
    cudaGetSymbolAddress((void**)&xpart,  g_xpart);

    __nv_bfloat16 *mo_h, *mo_l, *cat_h, *cat_l, *hh, *hl;
    __nv_bfloat16 *ln_h, *ln_l, *xc_h, *xc_l, *y_h, *y_l;
    __nv_bfloat16 *wupT_h, *wupT_l, *wb_h, *wb_l;
    cudaGetSymbolAddress((void**)&mo_h, g_mo_h);   cudaGetSymbolAddress((void**)&mo_l, g_mo_l);
    cudaGetSymbolAddress((void**)&cat_h, g_cat_h); cudaGetSymbolAddress((void**)&cat_l, g_cat_l);
    cudaGetSymbolAddress((void**)&hh,   g_hh);     cudaGetSymbolAddress((void**)&hl,   g_hl);
    cudaGetSymbolAddress((void**)&ln_h, g_lnh);    cudaGetSymbolAddress((void**)&ln_l, g_lnl);
    cudaGetSymbolAddress((void**)&xc_h, g_xch);    cudaGetSymbolAddress((void**)&xc_l, g_xcl);
    cudaGetSymbolAddress((void**)&y_h,  g_yh);     cudaGetSymbolAddress((void**)&y_l,  g_yl);
    cudaGetSymbolAddress((void**)&wupT_h, g_wupT_h); cudaGetSymbolAddress((void**)&wupT_l, g_wupT_l);
    cudaGetSymbolAddress((void**)&wb_h, g_wb_h);   cudaGetSymbolAddress((void**)&wb_l, g_wb_l);

    cudaFuncSetAttribute(tgemm_k, cudaFuncAttributeMaxDynamicSharedMemorySize,
                         TGV_SMEM);

    // ---- weight + input conversion ----
    weights_conv_k<<<WB_TOTAL / 256, 256>>>(w1, w2, in_proj_w, x_proj_w,
                                            out_proj_w, wb_h, wb_l);
    transpose_wup_k<<<dim3(32, 16), dim3(32, 8)>>>(w_up, wupT_h, wupT_l);
    convert_pair_k<<<(4096 * 512 / 4) / 256, 256>>>(motion, mo_h, mo_l);
    convert_skip_k<<<(ROWS * 512 / 4) / 256, 256>>>(skip, cat_h, cat_l);

    // 1) up = motion @ w_up
    tgemm_k<<<dim3(8, 32), 256, TGV_SMEM>>>(
        mo_h, mo_l, 512, wupT_h, wupT_l, 512, up_tmp, 1024,
        nullptr, nullptr, 512, 0, 0);

    // 2) rearrange + b_up -> cat cols 0..511
    up_rearrange_k<<<(ROWS * 512) / 256, 256>>>(up_tmp, b_up, cat_h, cat_l);

    // 3) h = [up|skip] @ w1^T + b1   (single K=1024 GEMM)
    tgemm_k<<<dim3(4, 64), 256, TGV_SMEM>>>(
        cat_h, cat_l, 1024, wb_h + OFF_W1, wb_l + OFF_W1, 1024, h, 512,
        b1, nullptr, 1024, 0, 0);

    // 4) silu(rmsnorm(h)) -> bf16 pair
    rmsnorm_silu_k<<<ROWS, 128>>>(h, rms_w, hh, hl);

    // 5) x = h @ w2^T + b2 + embed[b]
    tgemm_k<<<dim3(4, 64), 256, TGV_SMEM>>>(
        hh, hl, 512, wb_h + OFF_W2, wb_l + OFF_W2, 512, x, 512,
        b2, embed, 512, 0, 0);

    // 6) mamba layers
    for (int i = 0; i < NDEPTH; i++) {
        layernorm_bf_k<<<ROWS, 128>>>(x, ln_w + i * 512, ln_b + i * 512, ln_h, ln_l);

        tgemm_k<<<dim3(16, 64), 256, TGV_SMEM>>>(
            ln_h, ln_l, 512,
            wb_h + OFF_IP + (size_t)i * SZ_IP, wb_l + OFF_IP + (size_t)i * SZ_IP, 512,
            xz, 2048, nullptr, nullptr, 512, 0, 0);

        conv_silu_k<<<(ROWS * DI) / 256, 256>>>(
            xz, conv_w + (size_t)i * 1024 * 4, conv_b + i * 1024, xc, xc_h, xc_l);

        // x_proj split-K=4
        tgemm_k<<<dim3(1, 64, 4), 256, TGV_SMEM>>>(
            xc_h, xc_l, 1024,
            wb_h + OFF_XP + (size_t)i * SZ_XP, wb_l + OFF_XP + (size_t)i * SZ_XP, 1024,
            xpart, 128, nullptr, nullptr, 256, 0, ROWS * 128);
        reduce4_k<<<(ROWS * 64 / 4) / 256, 256>>>(xpart, xdbc);

        // scan with fused (batched) dt_proj + softplus
        scan_k<<<256, 128>>>(
            xc, xz, xdbc,
            dt_proj_w + (size_t)i * 1024 * 32, dt_proj_b + i * 1024,
            A_log + (size_t)i * 1024 * 16, D_param + i * 1024, y_h, y_l);

        tgemm_k<<<dim3(4, 64), 256, TGV_SMEM>>>(
            y_h, y_l, 1024,
            wb_h + OFF_OP + (size_t)i * SZ_OP, wb_l + OFF_OP + (size_t)i * SZ_OP, 1024,
            x, 512, out_proj_b + i * 512, nullptr, 1024, 1, 0);
    }

    // 7) final layernorm -> output
    layernorm_k<<<ROWS, 128>>>(x, norm_f_w, norm_f_b, out);
}